// round 11
// baseline (speedup 1.0000x reference)
#include <cuda_runtime.h>
#include <math.h>

// Problem constants
#define B   32
#define QL  16
#define KL  8192
#define D   512
#define INV_SQRT_D 0.044194173824159216f   // 1/sqrt(512)

// score kernel: av-style column streaming (proven 6.65 TB/s)
#define KSPLIT_S 32
#define KCHUNK_S (KL / KSPLIT_S)     // 256 rows per block
#define TROWS    8                   // rows per smem tile
#define NTILES   (KCHUNK_S / TROWS)  // 32
#define ZPB      4                   // z partials per block (one per warp)

// av kernel split
#define KSPLIT_V 32
#define KCHUNK_V (KL / KSPLIT_V)     // 256

// Scratch (device globals; allocations forbidden)
__device__ float g_w[B * KL];                      // 1 MB: p_k = exp(s_k)*t_k
__device__ float g_z[B * KSPLIT_S * ZPB];          // per-(block,warp) z partials
__device__ float g_acc[B * KSPLIT_V * D];          // 2 MB: weighted-V partials
__device__ int   g_cnt[B];                         // completion counters (self-resetting)

// ---------------------------------------------------------------------------
// Kernel A: p[b,k] = exp((q0.key[b,k])/sqrt(D)*t) * t  — av-style streaming.
// Thread t owns float4 column t, streams rows sequentially; per-row dot
// partials go through double-buffered smem tiles; cross-thread reduction
// overlaps the next tile's prefetch. UNCHANGED from R10 (83.9% DRAM).
// grid (KSPLIT_S, B), block 128.
// ---------------------------------------------------------------------------
__global__ void __launch_bounds__(128, 8)
score_kernel(const float* __restrict__ q,
             const float* __restrict__ key,
             const float* __restrict__ trust)
{
    const int b   = blockIdx.y;
    const int k0  = blockIdx.x * KCHUNK_S;
    const int tid = threadIdx.x;
    const int warp = tid >> 5;
    const int lane = tid & 31;

    __shared__ __align__(16) float ps[2][TROWS][128];   // 8 KB partial tiles
    __shared__ float ts[KCHUNK_S];                      // 1 KB trust chunk

    const float4 q4 = ((const float4*)(q + (size_t)b * QL * D))[tid];

    for (int i = tid; i < KCHUNK_S; i += 128)
        ts[i] = trust[(size_t)b * KL + k0 + i];

    const float4* kb = (const float4*)(key + ((size_t)b * KL + k0) * D) + tid;
    float* wb = g_w + (size_t)b * KL + k0;

    float zloc = 0.0f;          // valid on lane 0 of each warp
    float4 r[TROWS];

    #pragma unroll
    for (int j = 0; j < TROWS; j++) r[j] = kb[(size_t)j * (D / 4)];
    #pragma unroll
    for (int j = 0; j < TROWS; j++)
        ps[0][j][tid] = (r[j].x * q4.x + r[j].y * q4.y)
                      + (r[j].z * q4.z + r[j].w * q4.w);
    __syncthreads();

    for (int t = 0; t < NTILES; t++) {
        if (t + 1 < NTILES) {
            const float4* kn = kb + (size_t)(t + 1) * TROWS * (D / 4);
            #pragma unroll
            for (int j = 0; j < TROWS; j++) r[j] = kn[(size_t)j * (D / 4)];
        }

        const int buf = t & 1;
        #pragma unroll
        for (int rr = 0; rr < 2; rr++) {
            const int row = warp * 2 + rr;
            float4 v = ((const float4*)ps[buf][row])[lane];
            float s = (v.x + v.y) + (v.z + v.w);
            #pragma unroll
            for (int o = 16; o > 0; o >>= 1)
                s += __shfl_xor_sync(0xffffffffu, s, o);
            if (lane == 0) {
                const int gk = t * TROWS + row;
                const float tt = ts[gk];
                const float p = __expf(s * INV_SQRT_D * tt) * tt;
                wb[gk] = p;
                zloc += p;
            }
        }

        if (t + 1 < NTILES) {
            const int nbuf = (t + 1) & 1;
            #pragma unroll
            for (int j = 0; j < TROWS; j++)
                ps[nbuf][j][tid] = (r[j].x * q4.x + r[j].y * q4.y)
                                 + (r[j].z * q4.z + r[j].w * q4.w);
        }
        __syncthreads();
    }

    if (lane == 0)
        g_z[(size_t)(b * KSPLIT_S + blockIdx.x) * ZPB + warp] = zloc;
}

// ---------------------------------------------------------------------------
// Kernel B: split-K weighted value sum + fused final reduction.
// Main loop unchanged (the >=7 TB/s reference pattern). Afterwards, the LAST
// block to finish for batch b (threadfence-reduction pattern) sums the 32
// partials in fixed order, computes Z from the score z-partials, normalizes,
// writes out[b,:], and resets the counter (deterministic across replays).
// grid (KSPLIT_V, B), block 128.
// ---------------------------------------------------------------------------
__global__ void __launch_bounds__(128)
av_kernel(const float* __restrict__ value, float* __restrict__ out)
{
    const int b  = blockIdx.y;
    const int k0 = blockIdx.x * KCHUNK_V;
    const int tid = threadIdx.x;

    __shared__ float ws[KCHUNK_V];
    __shared__ bool  is_last;
    __shared__ float invZ_s;

    for (int i = tid; i < KCHUNK_V; i += 128)
        ws[i] = g_w[b * KL + k0 + i];
    __syncthreads();

    const float4* vb = (const float4*)(value + ((size_t)b * KL + k0) * D) + tid;

    float4 acc = make_float4(0.0f, 0.0f, 0.0f, 0.0f);
    #pragma unroll 16
    for (int kk = 0; kk < KCHUNK_V; kk++) {
        float4 v = vb[(size_t)kk * (D / 4)];
        float  w = ws[kk];
        acc.x += w * v.x;
        acc.y += w * v.y;
        acc.z += w * v.z;
        acc.w += w * v.w;
    }

    float4* out4 = (float4*)(g_acc + ((size_t)(b * KSPLIT_V + blockIdx.x)) * D);
    out4[tid] = acc;

    // --- last-block-per-batch final reduction (threadFenceReduction) ---
    __threadfence();
    __syncthreads();
    if (tid == 0) {
        int prev = atomicAdd(&g_cnt[b], 1);
        is_last = (prev == KSPLIT_V - 1);
    }
    __syncthreads();
    if (!is_last) return;
    __threadfence();   // acquire: make other blocks' partials visible

    // Z from the 128 score z-partials of this batch (fixed order)
    if (tid < 32) {
        const float* zb = g_z + (size_t)b * KSPLIT_S * ZPB;
        float z = 0.0f;
        #pragma unroll
        for (int i = 0; i < 4; i++) z += zb[tid + i * 32];
        #pragma unroll
        for (int o = 16; o > 0; o >>= 1)
            z += __shfl_xor_sync(0xffffffffu, z, o);
        if (tid == 0) invZ_s = 1.0f / z;
    }
    __syncthreads();
    const float invZ = invZ_s;

    // out[b,d], d = tid, tid+128, tid+256, tid+384; fixed-order partial sum
    #pragma unroll
    for (int j = 0; j < 4; j++) {
        const int d = tid + j * 128;
        float s = 0.0f;
        #pragma unroll
        for (int i = 0; i < KSPLIT_V; i++)
            s += g_acc[(size_t)(b * KSPLIT_V + i) * D + d];
        out[(size_t)b * D + d] = s * invZ;
    }

    if (tid == 0) g_cnt[b] = 0;   // reset for next graph replay
}

// ---------------------------------------------------------------------------
extern "C" void kernel_launch(void* const* d_in, const int* in_sizes, int n_in,
                              void* d_out, int out_size)
{
    const float* query = (const float*)d_in[0];   // (B, QL, D)
    const float* key   = (const float*)d_in[1];   // (B, KL, D)
    const float* value = (const float*)d_in[2];   // (B, KL, D)
    const float* trust = (const float*)d_in[3];   // (B, 1, KL)
    float* out = (float*)d_out;                   // (B, 1, D)

    (void)in_sizes; (void)n_in; (void)out_size;

    dim3 g1(KSPLIT_S, B);
    score_kernel<<<g1, 128>>>(query, key, trust);

    dim3 g2(KSPLIT_V, B);
    av_kernel<<<g2, 128>>>(value, out);
}